// round 9
// baseline (speedup 1.0000x reference)
#include <cuda_runtime.h>
#include <math.h>

#define NPASS 16
#define NFACE 640
#define NVERT 642
#define IMH 160
#define IMW 160
#define HW (IMH*IMW)
#define STEP (2.0f/159.0f)
#define GRID_ALL 640
#define TAUC (-0.002f)

// gaussian 11-tap weights (fp64 exp/normalize, rounded to float)
#define G0 1.4867195e-06f
#define G1 1.3383023e-04f
#define G2 4.4318484e-03f
#define G3 5.3990966e-02f
#define G4 2.4197073e-01f
#define G5 3.9894228e-01f
__device__ __constant__ float c_gauss[11]={G0,G1,G2,G3,G4,G5,G4,G3,G2,G1,G0};

// ---------------- scratch ----------------
__device__ float4 g_faceb[NPASS*NFACE*4];   // fallback path only
__device__ int    g_nvalid[NPASS];          // fallback path only
__device__ float  g_feats[NPASS*3*HW];
__device__ float  g_soft[NPASS*HW];
__device__ unsigned g_count = 0;            // persistent grid-barrier ticket

// ---------------- helpers ----------------
__device__ void quat_rod(const float* q, float scale, float* R){
    float w=q[0], x=q[1], y=q[2], z=q[3];
    float sn=sqrtf(x*x+y*y+z*z);
    float tt = 2.0f*((w<0.0f)? atan2f(-sn,-w) : atan2f(sn,w));
    float k = (sn>1e-8f)? (tt/fmaxf(sn,1e-8f)) : 2.0f;
    k *= scale;
    float ax=x*k, ay=y*k, az=z*k;
    float th=sqrtf(ax*ax+ay*ay+az*az);
    float inv=1.0f/fmaxf(th,1e-8f);
    float ux=ax*inv, uy=ay*inv, uz=az*inv;
    float s=sinf(th), c=cosf(th), cc=1.0f-c;
    R[0]=1.0f+cc*(-(uy*uy+uz*uz)); R[1]=-s*uz+cc*(ux*uy);          R[2]= s*uy+cc*(ux*uz);
    R[3]= s*uz+cc*(ux*uy);         R[4]=1.0f+cc*(-(ux*ux+uz*uz));  R[5]=-s*ux+cc*(uy*uz);
    R[6]=-s*uy+cc*(ux*uz);         R[7]= s*ux+cc*(uy*uz);          R[8]=1.0f+cc*(-(ux*ux+uy*uy));
}

__device__ void compute_RT(int p, const float* quat, const float* trans,
                           float* sR, float* sT){
    int f=p>>3, st=p&7;
    float R[9], Rs[9];
    quat_rod(&quat[(f*2+1)*4], 1.0f, R);
    quat_rod(&quat[(f*2+0)*4], 1.0f/16.0f, Rs);
    for(int s=0;s<st;s++){
        float Rn[9];
        for(int a=0;a<3;a++)
            for(int b=0;b<3;b++)
                Rn[a*3+b]=R[a*3+0]*Rs[0*3+b]+R[a*3+1]*Rs[1*3+b]+R[a*3+2]*Rs[2*3+b];
        for(int k=0;k<9;k++) R[k]=Rn[k];
    }
    for(int k=0;k<9;k++) sR[k]=R[k];
    float ti=(float)st*(1.0f/7.0f);
    for(int k=0;k<3;k++)
        sT[k]=trans[(f*2+1)*3+k] + ti*trans[(f*2+0)*3+k] - ((k==2)?2.0f:0.0f);
}

__device__ __forceinline__ bool face_record(const float* sv, const int* faces, int i,
                                            float4& r0, float4& r1, float4& r2){
    int i0=faces[i*3+0], i1=faces[i*3+1], i2=faces[i*3+2];
    float ax3=sv[i0*3], ay3=sv[i0*3+1], az3=sv[i0*3+2];
    float bx3=sv[i1*3], by3=sv[i1*3+1], bz3=sv[i1*3+2];
    float cx3=sv[i2*3], cy3=sv[i2*3+1], cz3=sv[i2*3+2];
    float nz=(bx3-ax3)*(cy3-ay3)-(by3-ay3)*(cx3-ax3);
    const float F=(float)(1.0/tan(1.57/4.0));   // exact reference focal (NOT pi/8)
    float ax=(ax3*F)/(-az3), ay=(ay3*F)/(-az3);
    float bx=(bx3*F)/(-bz3), by=(by3*F)/(-bz3);
    float cx=(cx3*F)/(-cz3), cy=(cy3*F)/(-cz3);
    float denom=(bx-ax)*(cy-ay)-(by-ay)*(cx-ax);
    bool valid=(nz>0.0f)&&(fabsf(denom)>1e-9f);
    if(valid){
        float inv=1.0f/denom;
        r0=make_float4((bx*cy-by*cx)*inv, (by-cy)*inv, (cx-bx)*inv, az3);
        r1=make_float4((cx*ay-cy*ax)*inv, (cy-ay)*inv, (ax-cx)*inv, bz3);
        r2=make_float4((ax*by-ay*bx)*inv, (ay-by)*inv, (bx-ax)*inv, cz3);
    }
    return valid;
}

// ---------------- post task: 8-row tile, rgb blur (t<960) or mask chain ----------------
// bufA >= 30*160, bufB >= 28*160
__device__ void post_task8(float* bufA, float* bufB, int t,
                           float* __restrict__ out, int tid, int nt){
    if(t<960){
        int img=t/20, tile=t%20, y0=tile*8;
        const float* in=&g_feats[img*HW];
        for(int idx=tid; idx<18*160; idx+=nt){
            int r=idx/160, x=idx%160;
            int yy=y0-5+r;
            yy = yy<0 ? -yy : (yy>IMH-1 ? 2*(IMH-1)-yy : yy);
            bufA[idx]=in[yy*IMW+x];
        }
        __syncthreads();
        for(int idx=tid; idx<8*160; idx+=nt){
            int j=idx/160, x=idx%160;
            float acc=0.f;
            #pragma unroll
            for(int k=0;k<11;k++) acc += c_gauss[k]*bufA[(j+k)*160+x];
            bufB[idx]=acc;
        }
        __syncthreads();
        int p=img/3, c=img%3;
        float* o=&out[(p*4+c)*HW];
        for(int idx=tid; idx<8*160; idx+=nt){
            int j=idx/160, x=idx%160;
            float acc=0.f;
            #pragma unroll
            for(int k=0;k<11;k++){
                int xx=x+k-5;
                xx = xx<0 ? -xx : (xx>IMW-1 ? 2*(IMW-1)-xx : xx);
                acc += c_gauss[k]*bufB[j*160+xx];
            }
            o[(y0+j)*IMW+x]=acc;
        }
    } else {
        int mt=t-960;
        int p=mt/20, tile=mt%20, y0=tile*8;
        const float* in=&g_soft[p*HW];
        // 1. soft rows [y0-11, y0+18] (valid only) -> bufA base y0-11 (30 rows)
        for(int idx=tid; idx<30*160; idx+=nt){
            int r=idx/160, x=idx%160;
            int yy=y0-11+r;
            if(yy>=0 && yy<IMH) bufA[idx]=in[yy*IMW+x];
        }
        __syncthreads();
        // 2. erode rows [y0-10, y0+17] (valid only) -> bufB base y0-10 (28 rows)
        for(int idx=tid; idx<28*160; idx+=nt){
            int r=idx/160, x=idx%160;
            int yy=y0-10+r;
            if(yy<0 || yy>=IMH) continue;
            float mval=3.4e38f;
            #pragma unroll
            for(int dy=-1;dy<=1;dy++){
                int ry=yy+dy; if(ry<0||ry>=IMH) continue;
                int sr=ry-(y0-11);
                #pragma unroll
                for(int dx=-1;dx<=1;dx++){
                    int xx=x+dx; if(xx<0||xx>=IMW) continue;
                    mval=fminf(mval, bufA[sr*160+xx]);
                }
            }
            bufB[idx]=mval;
        }
        __syncthreads();
        // 3. blurV1 rows [y0-5, y0+12] (valid only) -> bufA base y0-5 (18 rows)
        for(int idx=tid; idx<18*160; idx+=nt){
            int r=idx/160, x=idx%160;
            int yb=y0-5+r;
            if(yb<0 || yb>=IMH) continue;
            float acc=0.f;
            #pragma unroll
            for(int k=0;k<11;k++){
                int yy=yb+k-5;
                yy = yy<0 ? -yy : (yy>IMH-1 ? 2*(IMH-1)-yy : yy);
                acc += c_gauss[k]*bufB[(yy-(y0-10))*160+x];
            }
            bufA[idx]=acc;
        }
        __syncthreads();
        // 4. blurH1 rows [y0-5, y0+12] (valid only) -> bufB base y0-5 (18 rows)
        for(int idx=tid; idx<18*160; idx+=nt){
            int r=idx/160, x=idx%160;
            int yb=y0-5+r;
            if(yb<0 || yb>=IMH) continue;
            float acc=0.f;
            #pragma unroll
            for(int k=0;k<11;k++){
                int xx=x+k-5;
                xx = xx<0 ? -xx : (xx>IMW-1 ? 2*(IMW-1)-xx : xx);
                acc += c_gauss[k]*bufA[r*160+xx];
            }
            bufB[idx]=acc;
        }
        __syncthreads();
        // 5. blurV2 rows [y0, y0+7] -> bufA base y0 (8 rows)
        for(int idx=tid; idx<8*160; idx+=nt){
            int j=idx/160, x=idx%160;
            int yb=y0+j;
            float acc=0.f;
            #pragma unroll
            for(int k=0;k<11;k++){
                int yy=yb+k-5;
                yy = yy<0 ? -yy : (yy>IMH-1 ? 2*(IMH-1)-yy : yy);
                acc += c_gauss[k]*bufB[(yy-(y0-5))*160+x];
            }
            bufA[idx]=acc;
        }
        __syncthreads();
        // 6. blurH2 -> out channel 3
        float* o=&out[(p*4+3)*HW];
        for(int idx=tid; idx<8*160; idx+=nt){
            int j=idx/160, x=idx%160;
            float acc=0.f;
            #pragma unroll
            for(int k=0;k<11;k++){
                int xx=x+k-5;
                xx = xx<0 ? -xx : (xx>IMW-1 ? 2*(IMW-1)-xx : xx);
                acc += c_gauss[k]*bufA[j*160+xx];
            }
            o[(y0+j)*IMW+x]=acc;
        }
    }
}

// ---------------- unified single-launch kernel (640 blocks x 128 threads) ----------------
// dyn smem carve: s0|s1|s2 (3*640*16=30720) then {sv(7704) aliased by lists(4*640*4=10240)}
#define SMEM_ALL (30720+10240)

__global__ void __launch_bounds__(128,5) k_all(const float* __restrict__ uv,
                                               const int* __restrict__ faces,
                                               const float* __restrict__ quat,
                                               const float* __restrict__ trans,
                                               const float* __restrict__ ffeat,
                                               float* __restrict__ out){
    extern __shared__ __align__(16) char dsm[];
    float4* s0=(float4*)dsm;
    float4* s1=s0+NFACE;
    float4* s2=s1+NFACE;
    float*  sv=(float*)(s2+NFACE);
    int*  lists=(int*)(s2+NFACE);
    __shared__ float sR[9], sT[3];

    int bx=blockIdx.x;
    int p=bx/40, band=bx%40;
    int tid=threadIdx.x;
    int lane=tid&31, wid=tid>>5;

    // ---- phase A: rotation/translation ----
    if(tid==0) compute_RT(p, quat, trans, sR, sT);
    __syncthreads();
    // ---- phase B: vertices ----
    for(int n=tid; n<NVERT; n+=128){
        float ux=uv[n*3+0], uy=uv[n*3+1], uz=uv[n*3+2];
        sv[n*3+0]=sR[0]*ux+sR[1]*uy+sR[2]*uz + sT[0];
        sv[n*3+1]=sR[3]*ux+sR[4]*uy+sR[5]*uz + sT[1];
        sv[n*3+2]=sR[6]*ux+sR[7]*uy+sR[8]*uz + sT[2];
    }
    __syncthreads();
    // ---- phase C: face records (indexed by original face id; invalid -> sentinel) ----
    for(int f=tid; f<NFACE; f+=128){
        float4 r0,r1,r2;
        if(!face_record(sv, faces, f, r0, r1, r2)){
            r0=make_float4(-1e9f,0.f,0.f,0.f);
            r1=r0; r2=r0;
        }
        s0[f]=r0; s1[f]=r1; s2[f]=r2;
    }
    __syncthreads();   // records done; sv dead -> lists may overwrite

    // ---- phase D: per-warp row list (warp wid owns row y) ----
    int y=band*4+wid;
    float pyv=1.0f-(float)y*STEP;
    int* mylist=lists+wid*NFACE;
    int cnt=0;
    for(int base=0; base<NFACE; base+=32){
        int f=base+lane;
        float4 r0=s0[f], r1=s1[f], r2=s2[f];
        float lo=0.0f, hi=159.0f;
        #define EDGE(r) { \
            float a=(r).x-(r).y+(r).z*pyv; \
            float b=(r).y*STEP; \
            float tt=__fdividef(TAUC-a, b); \
            if(b>0.0f)      lo=fmaxf(lo,tt); \
            else if(b<0.0f) hi=fminf(hi,tt); \
            else if(a<TAUC) lo=3.0e38f; }
        EDGE(r0) EDGE(r1) EDGE(r2)
        #undef EDGE
        float slack=2.0f+2e-6f*(fabsf(lo)+fabsf(hi));
        bool keep=(lo<=hi+slack);
        unsigned bal=__ballot_sync(0xffffffffu, keep);
        if(keep){
            int pos=cnt+__popc(bal&((1u<<lane)-1u));
            mylist[pos]=f;
        }
        cnt+=__popc(bal);
    }

    // ---- phase E: raster (5 samples/thread, x = lane + 32*i) ----
    float px0=fmaf((float)lane, STEP, -1.0f);
    float pxs[5];
    #pragma unroll
    for(int i=0;i<5;i++) pxs[i]=px0+(32.0f*STEP)*(float)i;
    float mm[5], bzv[5]; int biv[5];
    #pragma unroll
    for(int i=0;i<5;i++){ mm[i]=TAUC; bzv[i]=-1e9f; biv[i]=-1; }

    for(int j=0;j<cnt;j++){
        int f=mylist[j];
        float4 a=s0[f], b=s1[f], c=s2[f];
        float w0b=fmaf(a.z,pyv,a.x);
        float w1b=fmaf(b.z,pyv,b.x);
        float w2b=fmaf(c.z,pyv,c.x);
        #pragma unroll
        for(int i=0;i<5;i++){
            float w0=fmaf(a.y,pxs[i],w0b);
            float w1=fmaf(b.y,pxs[i],w1b);
            float w2=fmaf(c.y,pxs[i],w2b);
            float mn=fminf(w0,fminf(w1,w2));
            mm[i]=fmaxf(mm[i],mn);
            float z=fmaf(c.w,w2,fmaf(b.w,w1,a.w*w0));
            if(mn>=-1e-6f && z>bzv[i]){ bzv[i]=z; biv[i]=f; }
        }
    }

    #pragma unroll
    for(int i=0;i<5;i++){
        int x=lane+32*i;
        float soft=1.0f/(1.0f+expf(-7000.0f*mm[i]));
        g_soft[p*HW + y*IMW + x]=soft;
        float f0=0.f,f1=0.f,f2=0.f;
        if(biv[i]>=0){
            float4 a=s0[biv[i]], b=s1[biv[i]], c=s2[biv[i]];
            float pxv=fmaf((float)x, STEP, -1.0f);
            float w0=fmaf(a.y,pxv,fmaf(a.z,pyv,a.x));
            float w1=fmaf(b.y,pxv,fmaf(b.z,pyv,b.x));
            float w2=fmaf(c.y,pxv,fmaf(c.z,pyv,c.x));
            const float* ff=&ffeat[biv[i]*9];
            f0=w0*ff[0]+w1*ff[3]+w2*ff[6];
            f1=w0*ff[1]+w1*ff[4]+w2*ff[7];
            f2=w0*ff[2]+w1*ff[5]+w2*ff[8];
        }
        int bo=p*3*HW + y*IMW + x;
        g_feats[bo      ]=f0;
        g_feats[bo+  HW ]=f1;
        g_feats[bo+2*HW ]=f2;
    }

    // ---- grid barrier (640 blocks co-resident) ----
    __syncthreads();
    __threadfence();
    if(tid==0){
        unsigned arrival=atomicAdd(&g_count, 1u);
        unsigned target=(arrival/GRID_ALL + 1u)*GRID_ALL;
        while(*((volatile unsigned*)&g_count) < target) __nanosleep(32);
    }
    __syncthreads();

    // ---- phase F: post (2 tasks of 1280) ----
    float* bufA=(float*)dsm;
    float* bufB=bufA+30*160;
    for(int t=bx; t<1280; t+=GRID_ALL){
        __syncthreads();
        post_task8(bufA, bufB, t, out, tid, 128);
    }
}

// ================= fallback 3-kernel path (round-6 proven structure) =================
__global__ void __launch_bounds__(640) k_geom(const float* __restrict__ uv,
                                              const int* __restrict__ faces,
                                              const float* __restrict__ quat,
                                              const float* __restrict__ trans){
    int p=blockIdx.x; int i=threadIdx.x;
    __shared__ float sR[9], sT[3];
    __shared__ float sv[NVERT*3];
    __shared__ int wcnt[20], wbase[20];
    if(i==0) compute_RT(p, quat, trans, sR, sT);
    __syncthreads();
    for(int n=i; n<NVERT; n+=640){
        float ux=uv[n*3+0], uy=uv[n*3+1], uz=uv[n*3+2];
        sv[n*3+0]=sR[0]*ux+sR[1]*uy+sR[2]*uz + sT[0];
        sv[n*3+1]=sR[3]*ux+sR[4]*uy+sR[5]*uz + sT[1];
        sv[n*3+2]=sR[6]*ux+sR[7]*uy+sR[8]*uz + sT[2];
    }
    __syncthreads();
    int lane=i&31, wid=i>>5;
    float4 r0,r1,r2;
    bool valid=face_record(sv, faces, i, r0, r1, r2);
    unsigned bal=__ballot_sync(0xffffffffu, valid);
    if(lane==0) wcnt[wid]=__popc(bal);
    __syncthreads();
    if(i==0){
        int acc=0;
        for(int w=0;w<20;w++){ wbase[w]=acc; acc+=wcnt[w]; }
        g_nvalid[p]=acc;
    }
    __syncthreads();
    if(valid){
        int pos=wbase[wid]+__popc(bal&((1u<<lane)-1u));
        float4* rec=&g_faceb[(p*NFACE+pos)*4];
        rec[0]=r0; rec[1]=r1; rec[2]=r2;
        rec[3]=make_float4(__int_as_float(i), 0.f, 0.f, 0.f);
    }
}

__global__ void __launch_bounds__(256) k_raster_fb(const float* __restrict__ ffeat){
    int p=blockIdx.z;
    int y0=blockIdx.y*8;
    int tx=threadIdx.x;
    int y=y0+threadIdx.y;
    int tid=threadIdx.y*32+tx;

    __shared__ float4 s0[NFACE], s1[NFACE], s2[NFACE];
    __shared__ int   sid[NFACE];

    int n=g_nvalid[p];
    const float4* src=&g_faceb[p*NFACE*4];
    for(int i=tid;i<n;i+=256){
        s0[i]=src[4*i+0]; s1[i]=src[4*i+1]; s2[i]=src[4*i+2];
        sid[i]=__float_as_int(src[4*i+3].x);
    }
    __syncthreads();

    float pyv = 1.0f - (float)y*STEP;
    float px0 = fmaf((float)tx, STEP, -1.0f);
    float pxs[5];
    #pragma unroll
    for(int i=0;i<5;i++) pxs[i]=px0+(32.0f*STEP)*(float)i;
    float mm[5], bzv[5]; int biv[5];
    #pragma unroll
    for(int i=0;i<5;i++){ mm[i]=-3.0e38f; bzv[i]=-1e9f; biv[i]=-1; }

    for(int f=0; f<n; f++){
        float4 a=s0[f], b=s1[f], c=s2[f];
        float w0b=fmaf(a.z,pyv,a.x);
        float w1b=fmaf(b.z,pyv,b.x);
        float w2b=fmaf(c.z,pyv,c.x);
        #pragma unroll
        for(int i=0;i<5;i++){
            float w0=fmaf(a.y,pxs[i],w0b);
            float w1=fmaf(b.y,pxs[i],w1b);
            float w2=fmaf(c.y,pxs[i],w2b);
            float mn=fminf(w0,fminf(w1,w2));
            mm[i]=fmaxf(mm[i],mn);
            float z=fmaf(c.w,w2,fmaf(b.w,w1,a.w*w0));
            if(mn>=-1e-6f && z>bzv[i]){ bzv[i]=z; biv[i]=f; }
        }
    }

    #pragma unroll
    for(int i=0;i<5;i++){
        int x=tx+32*i;
        float soft=1.0f/(1.0f+expf(-7000.0f*mm[i]));
        g_soft[p*HW + y*IMW + x]=soft;
        float f0=0.f,f1=0.f,f2=0.f;
        if(biv[i]>=0){
            float4 a=s0[biv[i]], b=s1[biv[i]], c=s2[biv[i]];
            float pxv=fmaf((float)x, STEP, -1.0f);
            float w0=fmaf(a.y,pxv,fmaf(a.z,pyv,a.x));
            float w1=fmaf(b.y,pxv,fmaf(b.z,pyv,b.x));
            float w2=fmaf(c.y,pxv,fmaf(c.z,pyv,c.x));
            const float* ff=&ffeat[sid[biv[i]]*9];
            f0=w0*ff[0]+w1*ff[3]+w2*ff[6];
            f1=w0*ff[1]+w1*ff[4]+w2*ff[7];
            f2=w0*ff[2]+w1*ff[5]+w2*ff[8];
        }
        int bo=p*3*HW + y*IMW + x;
        g_feats[bo      ]=f0;
        g_feats[bo+  HW ]=f1;
        g_feats[bo+2*HW ]=f2;
    }
}

__global__ void __launch_bounds__(128) k_post_fb(float* __restrict__ out){
    __shared__ float bufA[30*160];
    __shared__ float bufB[28*160];
    post_task8(bufA, bufB, blockIdx.x, out, threadIdx.x, 128);
}

// ---------------- launch ----------------
extern "C" void kernel_launch(void* const* d_in, const int* in_sizes, int n_in,
                              void* d_out, int out_size) {
    const float* trans=(const float*)d_in[0];
    const float* quat =(const float*)d_in[1];
    const float* uv   =(const float*)d_in[2];
    const float* ffeat=(const float*)d_in[3];
    const int*   faces=(const int*)  d_in[4];
    float* out=(float*)d_out;

    cudaFuncSetAttribute(k_all, cudaFuncAttributeMaxDynamicSharedMemorySize, SMEM_ALL);
    int dev=0; cudaGetDevice(&dev);
    int nsm=0; cudaDeviceGetAttribute(&nsm, cudaDevAttrMultiProcessorCount, dev);
    int per_sm=0;
    cudaOccupancyMaxActiveBlocksPerMultiprocessor(&per_sm, k_all, 128, SMEM_ALL);
    if((long)per_sm*nsm >= GRID_ALL){
        k_all<<<GRID_ALL, 128, SMEM_ALL>>>(uv, faces, quat, trans, ffeat, out);
    } else {
        k_geom<<<NPASS, 640>>>(uv, faces, quat, trans);
        k_raster_fb<<<dim3(1,20,NPASS), dim3(32,8)>>>(ffeat);
        k_post_fb<<<1280, 128>>>(out);
    }
}

// round 10
// speedup vs baseline: 1.5893x; 1.5893x over previous
#include <cuda_runtime.h>
#include <math.h>

#define NPASS 16
#define NFACE 640
#define NVERT 642
#define IMH 160
#define IMW 160
#define HW (IMH*IMW)
#define STEP (2.0f/159.0f)
#define GRID_ALL 320

// gaussian 11-tap weights (fp64 exp/normalize, rounded to float)
#define G0 1.4867195e-06f
#define G1 1.3383023e-04f
#define G2 4.4318484e-03f
#define G3 5.3990966e-02f
#define G4 2.4197073e-01f
#define G5 3.9894228e-01f
__device__ __constant__ float c_gauss[11]={G0,G1,G2,G3,G4,G5,G4,G3,G2,G1,G0};

// ---------------- scratch ----------------
__device__ float4 g_faceb[NPASS*NFACE*4];   // fallback path only
__device__ int    g_nvalid[NPASS];          // fallback path only
__device__ float  g_feats[NPASS*3*HW];
__device__ float  g_soft[NPASS*HW];
__device__ unsigned g_count = 0;            // persistent grid-barrier ticket

// ---------------- helpers ----------------
__device__ void quat_rod(const float* q, float scale, float* R){
    float w=q[0], x=q[1], y=q[2], z=q[3];
    float sn=sqrtf(x*x+y*y+z*z);
    float tt = 2.0f*((w<0.0f)? atan2f(-sn,-w) : atan2f(sn,w));
    float k = (sn>1e-8f)? (tt/fmaxf(sn,1e-8f)) : 2.0f;
    k *= scale;
    float ax=x*k, ay=y*k, az=z*k;
    float th=sqrtf(ax*ax+ay*ay+az*az);
    float inv=1.0f/fmaxf(th,1e-8f);
    float ux=ax*inv, uy=ay*inv, uz=az*inv;
    float s=sinf(th), c=cosf(th), cc=1.0f-c;
    R[0]=1.0f+cc*(-(uy*uy+uz*uz)); R[1]=-s*uz+cc*(ux*uy);          R[2]= s*uy+cc*(ux*uz);
    R[3]= s*uz+cc*(ux*uy);         R[4]=1.0f+cc*(-(ux*ux+uz*uz));  R[5]=-s*ux+cc*(uy*uz);
    R[6]=-s*uy+cc*(ux*uz);         R[7]= s*ux+cc*(uy*uz);          R[8]=1.0f+cc*(-(ux*ux+uy*uy));
}

__device__ void compute_RT(int p, const float* quat, const float* trans,
                           float* sR, float* sT){
    int f=p>>3, st=p&7;
    float R[9], Rs[9];
    quat_rod(&quat[(f*2+1)*4], 1.0f, R);
    quat_rod(&quat[(f*2+0)*4], 1.0f/16.0f, Rs);
    for(int s=0;s<st;s++){
        float Rn[9];
        for(int a=0;a<3;a++)
            for(int b=0;b<3;b++)
                Rn[a*3+b]=R[a*3+0]*Rs[0*3+b]+R[a*3+1]*Rs[1*3+b]+R[a*3+2]*Rs[2*3+b];
        for(int k=0;k<9;k++) R[k]=Rn[k];
    }
    for(int k=0;k<9;k++) sR[k]=R[k];
    float ti=(float)st*(1.0f/7.0f);
    for(int k=0;k<3;k++)
        sT[k]=trans[(f*2+1)*3+k] + ti*trans[(f*2+0)*3+k] - ((k==2)?2.0f:0.0f);
}

// face record with z-plane coefficients packed in .w: (Za,Zb,Zc) in (r0.w,r1.w,r2.w)
__device__ __forceinline__ bool face_record(const float* sv, const int* faces, int i,
                                            float4& r0, float4& r1, float4& r2){
    int i0=faces[i*3+0], i1=faces[i*3+1], i2=faces[i*3+2];
    float ax3=sv[i0*3], ay3=sv[i0*3+1], az3=sv[i0*3+2];
    float bx3=sv[i1*3], by3=sv[i1*3+1], bz3=sv[i1*3+2];
    float cx3=sv[i2*3], cy3=sv[i2*3+1], cz3=sv[i2*3+2];
    float nz=(bx3-ax3)*(cy3-ay3)-(by3-ay3)*(cx3-ax3);
    const float F=(float)(1.0/tan(1.57/4.0));   // exact reference focal (NOT pi/8)
    float ax=(ax3*F)/(-az3), ay=(ay3*F)/(-az3);
    float bx=(bx3*F)/(-bz3), by=(by3*F)/(-bz3);
    float cx=(cx3*F)/(-cz3), cy=(cy3*F)/(-cz3);
    float denom=(bx-ax)*(cy-ay)-(by-ay)*(cx-ax);
    bool valid=(nz>0.0f)&&(fabsf(denom)>1e-9f);
    if(valid){
        float inv=1.0f/denom;
        float A0=(bx*cy-by*cx)*inv, B0=(by-cy)*inv, C0=(cx-bx)*inv;
        float A1=(cx*ay-cy*ax)*inv, B1=(cy-ay)*inv, C1=(ax-cx)*inv;
        float A2=(ax*by-ay*bx)*inv, B2=(ay-by)*inv, C2=(bx-ax)*inv;
        float Za=A0*az3+A1*bz3+A2*cz3;
        float Zb=B0*az3+B1*bz3+B2*cz3;
        float Zc=C0*az3+C1*bz3+C2*cz3;
        r0=make_float4(A0,B0,C0,Za);
        r1=make_float4(A1,B1,C1,Zb);
        r2=make_float4(A2,B2,C2,Zc);
    }
    return valid;
}

// ---------------- shared raster pixel-loop (z-plane, independent-FMA samples) ----------------
__device__ void raster_pixels(const float4* s0, const float4* s1, const float4* s2,
                              const int* sid, int m, int p, int y0, int tx, int ty,
                              const float* __restrict__ ffeat){
    int y=y0+ty;
    float pyv = 1.0f - (float)y*STEP;
    float px0 = fmaf((float)tx, STEP, -1.0f);
    float pxs[5];
    #pragma unroll
    for(int i=0;i<5;i++) pxs[i]=px0+(32.0f*STEP)*(float)i;
    float mm[5], bzv[5]; int biv[5];
    #pragma unroll
    for(int i=0;i<5;i++){ mm[i]=-3.0e38f; bzv[i]=-1e9f; biv[i]=-1; }

    for(int f=0; f<m; f++){
        float4 a=s0[f], b=s1[f], c=s2[f];
        float w0b=fmaf(a.z,pyv,a.x);
        float w1b=fmaf(b.z,pyv,b.x);
        float w2b=fmaf(c.z,pyv,c.x);
        float zb =fmaf(c.w,pyv,a.w);
        #pragma unroll
        for(int i=0;i<5;i++){
            float w0=fmaf(a.y,pxs[i],w0b);
            float w1=fmaf(b.y,pxs[i],w1b);
            float w2=fmaf(c.y,pxs[i],w2b);
            float mn=fminf(w0,fminf(w1,w2));
            mm[i]=fmaxf(mm[i],mn);
            float z=fmaf(b.w,pxs[i],zb);
            if(mn>=-1e-6f && z>bzv[i]){ bzv[i]=z; biv[i]=f; }
        }
    }

    #pragma unroll
    for(int i=0;i<5;i++){
        int x=tx+32*i;
        float soft=1.0f/(1.0f+expf(-7000.0f*mm[i]));
        g_soft[p*HW + y*IMW + x]=soft;
        float f0=0.f,f1=0.f,f2=0.f;
        if(biv[i]>=0){
            float4 a=s0[biv[i]], b=s1[biv[i]], c=s2[biv[i]];
            float pxv=fmaf((float)x, STEP, -1.0f);
            float w0=fmaf(a.y,pxv,fmaf(a.z,pyv,a.x));
            float w1=fmaf(b.y,pxv,fmaf(b.z,pyv,b.x));
            float w2=fmaf(c.y,pxv,fmaf(c.z,pyv,c.x));
            const float* ff=&ffeat[sid[biv[i]]*9];
            f0=w0*ff[0]+w1*ff[3]+w2*ff[6];
            f1=w0*ff[1]+w1*ff[4]+w2*ff[7];
            f2=w0*ff[2]+w1*ff[5]+w2*ff[8];
        }
        int bo=p*3*HW + y*IMW + x;
        g_feats[bo      ]=f0;
        g_feats[bo+  HW ]=f1;
        g_feats[bo+2*HW ]=f2;
    }
}

// ---------------- post task (16-row tile, rgb blur or mask chain) ----------------
__device__ void post_task(float* bufA, float* bufB, int task, int tile,
                          float* __restrict__ out, int tid){
    int y0=tile*16;
    if(task<48){
        const float* in=&g_feats[task*HW];
        for(int idx=tid; idx<26*160; idx+=256){
            int r=idx/160, x=idx%160;
            int yy=y0-5+r;
            yy = yy<0 ? -yy : (yy>IMH-1 ? 2*(IMH-1)-yy : yy);
            bufA[idx]=in[yy*IMW+x];
        }
        __syncthreads();
        for(int idx=tid; idx<16*160; idx+=256){
            int j=idx/160, x=idx%160;
            float acc=0.f;
            #pragma unroll
            for(int k=0;k<11;k++) acc += c_gauss[k]*bufA[(j+k)*160+x];
            bufB[idx]=acc;
        }
        __syncthreads();
        int p=task/3, c=task%3;
        float* o=&out[(p*4+c)*HW];
        for(int idx=tid; idx<16*160; idx+=256){
            int j=idx/160, x=idx%160;
            float acc=0.f;
            #pragma unroll
            for(int k=0;k<11;k++){
                int xx=x+k-5;
                xx = xx<0 ? -xx : (xx>IMW-1 ? 2*(IMW-1)-xx : xx);
                acc += c_gauss[k]*bufB[j*160+xx];
            }
            o[(y0+j)*IMW+x]=acc;
        }
    } else {
        int p=task-48;
        const float* in=&g_soft[p*HW];
        for(int idx=tid; idx<38*160; idx+=256){
            int r=idx/160, x=idx%160;
            int yy=y0-11+r;
            if(yy>=0 && yy<IMH) bufA[idx]=in[yy*IMW+x];
        }
        __syncthreads();
        for(int idx=tid; idx<36*160; idx+=256){
            int r=idx/160, x=idx%160;
            int yy=y0-10+r;
            if(yy<0 || yy>=IMH) continue;
            float mval=3.4e38f;
            #pragma unroll
            for(int dy=-1;dy<=1;dy++){
                int ry=yy+dy; if(ry<0||ry>=IMH) continue;
                int sr=ry-(y0-11);
                #pragma unroll
                for(int dx=-1;dx<=1;dx++){
                    int xx=x+dx; if(xx<0||xx>=IMW) continue;
                    mval=fminf(mval, bufA[sr*160+xx]);
                }
            }
            bufB[idx]=mval;
        }
        __syncthreads();
        for(int idx=tid; idx<26*160; idx+=256){
            int r=idx/160, x=idx%160;
            int yb=y0-5+r;
            if(yb<0 || yb>=IMH) continue;
            float acc=0.f;
            #pragma unroll
            for(int k=0;k<11;k++){
                int yy=yb+k-5;
                yy = yy<0 ? -yy : (yy>IMH-1 ? 2*(IMH-1)-yy : yy);
                acc += c_gauss[k]*bufB[(yy-(y0-10))*160+x];
            }
            bufA[idx]=acc;
        }
        __syncthreads();
        for(int idx=tid; idx<26*160; idx+=256){
            int r=idx/160, x=idx%160;
            int yb=y0-5+r;
            if(yb<0 || yb>=IMH) continue;
            float acc=0.f;
            #pragma unroll
            for(int k=0;k<11;k++){
                int xx=x+k-5;
                xx = xx<0 ? -xx : (xx>IMW-1 ? 2*(IMW-1)-xx : xx);
                acc += c_gauss[k]*bufA[r*160+xx];
            }
            bufB[idx]=acc;
        }
        __syncthreads();
        for(int idx=tid; idx<16*160; idx+=256){
            int j=idx/160, x=idx%160;
            int yb=y0+j;
            float acc=0.f;
            #pragma unroll
            for(int k=0;k<11;k++){
                int yy=yb+k-5;
                yy = yy<0 ? -yy : (yy>IMH-1 ? 2*(IMH-1)-yy : yy);
                acc += c_gauss[k]*bufB[(yy-(y0-5))*160+x];
            }
            bufA[idx]=acc;
        }
        __syncthreads();
        float* o=&out[(p*4+3)*HW];
        for(int idx=tid; idx<16*160; idx+=256){
            int j=idx/160, x=idx%160;
            float acc=0.f;
            #pragma unroll
            for(int k=0;k<11;k++){
                int xx=x+k-5;
                xx = xx<0 ? -xx : (xx>IMW-1 ? 2*(IMW-1)-xx : xx);
                acc += c_gauss[k]*bufA[j*160+xx];
            }
            o[(y0+j)*IMW+x]=acc;
        }
    }
}

// ---------------- unified single-launch kernel (round-7 structure) ----------------
struct GeomRaster {
    float  sv[NVERT*3];
    float4 s0[NFACE], s1[NFACE], s2[NFACE];
    int    sid[NFACE];
    float  R[9], T[3];
    int    warp_cnt[8], warp_off[8], chunk_base;
};
struct Post { float bufA[38*160]; float bufB[36*160]; };
union UShared { GeomRaster g; Post p; };

__global__ void __launch_bounds__(256,3) k_all(const float* __restrict__ uv,
                                               const int* __restrict__ faces,
                                               const float* __restrict__ quat,
                                               const float* __restrict__ trans,
                                               const float* __restrict__ ffeat,
                                               float* __restrict__ out){
    __shared__ UShared u;
    int bx=blockIdx.x;
    int p=bx/20, band=bx%20, y0=band*8;
    int tid=threadIdx.x;
    int tx=tid&31, ty=tid>>5;
    int lane=tid&31, wid=tid>>5;

    // ---- phase 1: per-block geometry ----
    if(tid==0){
        compute_RT(p, quat, trans, u.g.R, u.g.T);
        u.g.chunk_base=0;
    }
    __syncthreads();
    for(int n=tid; n<NVERT; n+=256){
        float ux=uv[n*3+0], uy=uv[n*3+1], uz=uv[n*3+2];
        u.g.sv[n*3+0]=u.g.R[0]*ux+u.g.R[1]*uy+u.g.R[2]*uz + u.g.T[0];
        u.g.sv[n*3+1]=u.g.R[3]*ux+u.g.R[4]*uy+u.g.R[5]*uz + u.g.T[1];
        u.g.sv[n*3+2]=u.g.R[6]*ux+u.g.R[7]*uy+u.g.R[8]*uz + u.g.T[2];
    }
    __syncthreads();

    float pyc = 1.0f - ((float)y0+3.5f)*STEP;
    float pyr = 3.5f*STEP + 1e-4f;
    const float TAU = -0.002f;

    for(int base=0; base<NFACE; base+=256){
        int fidx=base+tid;
        bool keep=false;
        float4 r0,r1,r2;
        if(fidx<NFACE){
            if(face_record(u.g.sv, faces, fidx, r0, r1, r2)){
                float u0=r0.x + fabsf(r0.y) + r0.z*pyc + fabsf(r0.z)*pyr;
                float u1=r1.x + fabsf(r1.y) + r1.z*pyc + fabsf(r1.z)*pyr;
                float u2=r2.x + fabsf(r2.y) + r2.z*pyc + fabsf(r2.z)*pyr;
                keep = fminf(u0,fminf(u1,u2)) >= TAU;
            }
        }
        unsigned bal=__ballot_sync(0xffffffffu, keep);
        if(lane==0) u.g.warp_cnt[wid]=__popc(bal);
        __syncthreads();
        if(tid==0){
            int a=u.g.chunk_base;
            for(int w=0;w<8;w++){ u.g.warp_off[w]=a; a+=u.g.warp_cnt[w]; }
            u.g.chunk_base=a;
        }
        __syncthreads();
        if(keep){
            int pos=u.g.warp_off[wid]+__popc(bal&((1u<<lane)-1u));
            u.g.s0[pos]=r0; u.g.s1[pos]=r1; u.g.s2[pos]=r2; u.g.sid[pos]=fidx;
        }
        __syncthreads();
    }
    int m=u.g.chunk_base;

    // ---- phase 2: raster ----
    raster_pixels(u.g.s0, u.g.s1, u.g.s2, u.g.sid, m, p, y0, tx, ty, ffeat);

    // ---- grid barrier (320 blocks co-resident) ----
    __syncthreads();
    __threadfence();
    if(tid==0){
        unsigned arrival=atomicAdd(&g_count, 1u);
        unsigned target=(arrival/GRID_ALL + 1u)*GRID_ALL;
        while(*((volatile unsigned*)&g_count) < target) __nanosleep(32);
    }
    __syncthreads();

    // ---- phase 3: post (2 tasks per block) ----
    for(int t=bx; t<640; t+=GRID_ALL){
        int tile=t%10, task=t/10;
        __syncthreads();
        post_task(u.p.bufA, u.p.bufB, task, tile, out, tid);
    }
}

// ================= fallback 3-kernel path =================
__global__ void __launch_bounds__(640) k_geom(const float* __restrict__ uv,
                                              const int* __restrict__ faces,
                                              const float* __restrict__ quat,
                                              const float* __restrict__ trans){
    int p=blockIdx.x; int i=threadIdx.x;
    __shared__ float sR[9], sT[3];
    __shared__ float sv[NVERT*3];
    __shared__ int wcnt[20], wbase[20];
    if(i==0) compute_RT(p, quat, trans, sR, sT);
    __syncthreads();
    for(int n=i; n<NVERT; n+=640){
        float ux=uv[n*3+0], uy=uv[n*3+1], uz=uv[n*3+2];
        sv[n*3+0]=sR[0]*ux+sR[1]*uy+sR[2]*uz + sT[0];
        sv[n*3+1]=sR[3]*ux+sR[4]*uy+sR[5]*uz + sT[1];
        sv[n*3+2]=sR[6]*ux+sR[7]*uy+sR[8]*uz + sT[2];
    }
    __syncthreads();
    int lane=i&31, wid=i>>5;
    float4 r0,r1,r2;
    bool valid=face_record(sv, faces, i, r0, r1, r2);
    unsigned bal=__ballot_sync(0xffffffffu, valid);
    if(lane==0) wcnt[wid]=__popc(bal);
    __syncthreads();
    if(i==0){
        int acc=0;
        for(int w=0;w<20;w++){ wbase[w]=acc; acc+=wcnt[w]; }
        g_nvalid[p]=acc;
    }
    __syncthreads();
    if(valid){
        int pos=wbase[wid]+__popc(bal&((1u<<lane)-1u));
        float4* rec=&g_faceb[(p*NFACE+pos)*4];
        rec[0]=r0; rec[1]=r1; rec[2]=r2;
        rec[3]=make_float4(__int_as_float(i), 0.f, 0.f, 0.f);
    }
}

__global__ void __launch_bounds__(256) k_raster_fb(const float* __restrict__ ffeat){
    int p=blockIdx.z;
    int y0=blockIdx.y*8;
    int tx=threadIdx.x;
    int tid=threadIdx.y*32+tx;

    __shared__ float4 s0[NFACE], s1[NFACE], s2[NFACE];
    __shared__ int   sid[NFACE];

    int n=g_nvalid[p];
    const float4* src=&g_faceb[p*NFACE*4];
    for(int i=tid;i<n;i+=256){
        s0[i]=src[4*i+0]; s1[i]=src[4*i+1]; s2[i]=src[4*i+2];
        sid[i]=__float_as_int(src[4*i+3].x);
    }
    __syncthreads();
    raster_pixels(s0, s1, s2, sid, n, p, y0, tx, threadIdx.y, ffeat);
}

__global__ void __launch_bounds__(256) k_post_fb(float* __restrict__ out){
    __shared__ float bufA[38*160];
    __shared__ float bufB[36*160];
    post_task(bufA, bufB, blockIdx.y, blockIdx.x, out, threadIdx.x);
}

// ---------------- launch ----------------
extern "C" void kernel_launch(void* const* d_in, const int* in_sizes, int n_in,
                              void* d_out, int out_size) {
    const float* trans=(const float*)d_in[0];
    const float* quat =(const float*)d_in[1];
    const float* uv   =(const float*)d_in[2];
    const float* ffeat=(const float*)d_in[3];
    const int*   faces=(const int*)  d_in[4];
    float* out=(float*)d_out;

    int dev=0; cudaGetDevice(&dev);
    int nsm=0; cudaDeviceGetAttribute(&nsm, cudaDevAttrMultiProcessorCount, dev);
    int per_sm=0;
    cudaOccupancyMaxActiveBlocksPerMultiprocessor(&per_sm, k_all, 256, 0);
    if((long)per_sm*nsm >= GRID_ALL){
        k_all<<<GRID_ALL, 256>>>(uv, faces, quat, trans, ffeat, out);
    } else {
        k_geom<<<NPASS, 640>>>(uv, faces, quat, trans);
        k_raster_fb<<<dim3(1,20,NPASS), dim3(32,8)>>>(ffeat);
        k_post_fb<<<dim3(10,64), 256>>>(out);
    }
}

// round 11
// speedup vs baseline: 1.5939x; 1.0029x over previous
#include <cuda_runtime.h>
#include <math.h>

#define NPASS 16
#define NFACE 640
#define NVERT 642
#define IMH 160
#define IMW 160
#define HW (IMH*IMW)
#define STEP (2.0f/159.0f)
#define GRID_ALL 320

// gaussian 11-tap weights (fp64 exp/normalize, rounded to float)
#define G0 1.4867195e-06f
#define G1 1.3383023e-04f
#define G2 4.4318484e-03f
#define G3 5.3990966e-02f
#define G4 2.4197073e-01f
#define G5 3.9894228e-01f
__device__ __constant__ float c_gauss[11]={G0,G1,G2,G3,G4,G5,G4,G3,G2,G1,G0};

// ---------------- scratch ----------------
__device__ float4 g_faceb[NPASS*NFACE*4];   // fallback path only
__device__ int    g_nvalid[NPASS];          // fallback path only
__device__ float  g_feats[NPASS*3*HW];
__device__ float  g_soft[NPASS*HW];
__device__ unsigned g_count = 0;            // persistent grid-barrier ticket

// ---------------- helpers ----------------
__device__ void quat_rod(const float* q, float scale, float* R){
    float w=q[0], x=q[1], y=q[2], z=q[3];
    float sn=sqrtf(x*x+y*y+z*z);
    float tt = 2.0f*((w<0.0f)? atan2f(-sn,-w) : atan2f(sn,w));
    float k = (sn>1e-8f)? (tt/fmaxf(sn,1e-8f)) : 2.0f;
    k *= scale;
    float ax=x*k, ay=y*k, az=z*k;
    float th=sqrtf(ax*ax+ay*ay+az*az);
    float inv=1.0f/fmaxf(th,1e-8f);
    float ux=ax*inv, uy=ay*inv, uz=az*inv;
    float s=sinf(th), c=cosf(th), cc=1.0f-c;
    R[0]=1.0f+cc*(-(uy*uy+uz*uz)); R[1]=-s*uz+cc*(ux*uy);          R[2]= s*uy+cc*(ux*uz);
    R[3]= s*uz+cc*(ux*uy);         R[4]=1.0f+cc*(-(ux*ux+uz*uz));  R[5]=-s*ux+cc*(uy*uz);
    R[6]=-s*uy+cc*(ux*uz);         R[7]= s*ux+cc*(uy*uz);          R[8]=1.0f+cc*(-(ux*ux+uy*uy));
}

__device__ void compute_RT(int p, const float* quat, const float* trans,
                           float* sR, float* sT){
    int f=p>>3, st=p&7;
    float R[9], Rs[9];
    quat_rod(&quat[(f*2+1)*4], 1.0f, R);
    quat_rod(&quat[(f*2+0)*4], 1.0f/16.0f, Rs);
    for(int s=0;s<st;s++){
        float Rn[9];
        for(int a=0;a<3;a++)
            for(int b=0;b<3;b++)
                Rn[a*3+b]=R[a*3+0]*Rs[0*3+b]+R[a*3+1]*Rs[1*3+b]+R[a*3+2]*Rs[2*3+b];
        for(int k=0;k<9;k++) R[k]=Rn[k];
    }
    for(int k=0;k<9;k++) sR[k]=R[k];
    float ti=(float)st*(1.0f/7.0f);
    for(int k=0;k<3;k++)
        sT[k]=trans[(f*2+1)*3+k] + ti*trans[(f*2+0)*3+k] - ((k==2)?2.0f:0.0f);
}

// face record with z-plane coefficients packed in .w: (Za,Zb,Zc) in (r0.w,r1.w,r2.w)
__device__ __forceinline__ bool face_record(const float* sv, const int* faces, int i,
                                            float4& r0, float4& r1, float4& r2){
    int i0=faces[i*3+0], i1=faces[i*3+1], i2=faces[i*3+2];
    float ax3=sv[i0*3], ay3=sv[i0*3+1], az3=sv[i0*3+2];
    float bx3=sv[i1*3], by3=sv[i1*3+1], bz3=sv[i1*3+2];
    float cx3=sv[i2*3], cy3=sv[i2*3+1], cz3=sv[i2*3+2];
    float nz=(bx3-ax3)*(cy3-ay3)-(by3-ay3)*(cx3-ax3);
    const float F=(float)(1.0/tan(1.57/4.0));   // exact reference focal (NOT pi/8)
    float ax=(ax3*F)/(-az3), ay=(ay3*F)/(-az3);
    float bx=(bx3*F)/(-bz3), by=(by3*F)/(-bz3);
    float cx=(cx3*F)/(-cz3), cy=(cy3*F)/(-cz3);
    float denom=(bx-ax)*(cy-ay)-(by-ay)*(cx-ax);
    bool valid=(nz>0.0f)&&(fabsf(denom)>1e-9f);
    if(valid){
        float inv=1.0f/denom;
        float A0=(bx*cy-by*cx)*inv, B0=(by-cy)*inv, C0=(cx-bx)*inv;
        float A1=(cx*ay-cy*ax)*inv, B1=(cy-ay)*inv, C1=(ax-cx)*inv;
        float A2=(ax*by-ay*bx)*inv, B2=(ay-by)*inv, C2=(bx-ax)*inv;
        float Za=A0*az3+A1*bz3+A2*cz3;
        float Zb=B0*az3+B1*bz3+B2*cz3;
        float Zc=C0*az3+C1*bz3+C2*cz3;
        r0=make_float4(A0,B0,C0,Za);
        r1=make_float4(A1,B1,C1,Zb);
        r2=make_float4(A2,B2,C2,Zc);
    }
    return valid;
}

// ---------------- shared raster pixel-loop (z-plane, face-loop unrolled x2) ----------------
__device__ void raster_pixels(const float4* s0, const float4* s1, const float4* s2,
                              const int* sid, int m, int p, int y0, int tx, int ty,
                              const float* __restrict__ ffeat){
    int y=y0+ty;
    float pyv = 1.0f - (float)y*STEP;
    float px0 = fmaf((float)tx, STEP, -1.0f);
    float pxs[5];
    #pragma unroll
    for(int i=0;i<5;i++) pxs[i]=px0+(32.0f*STEP)*(float)i;
    float mm[5], bzv[5]; int biv[5];
    #pragma unroll
    for(int i=0;i<5;i++){ mm[i]=-3.0e38f; bzv[i]=-1e9f; biv[i]=-1; }

    int f=0;
    for(; f+2<=m; f+=2){
        float4 a0=s0[f],   b0=s1[f],   c0=s2[f];
        float4 a1=s0[f+1], b1=s1[f+1], c1=s2[f+1];
        float w0b0=fmaf(a0.z,pyv,a0.x);
        float w1b0=fmaf(b0.z,pyv,b0.x);
        float w2b0=fmaf(c0.z,pyv,c0.x);
        float zb0 =fmaf(c0.w,pyv,a0.w);
        float w0b1=fmaf(a1.z,pyv,a1.x);
        float w1b1=fmaf(b1.z,pyv,b1.x);
        float w2b1=fmaf(c1.z,pyv,c1.x);
        float zb1 =fmaf(c1.w,pyv,a1.w);
        #pragma unroll
        for(int i=0;i<5;i++){
            float w00=fmaf(a0.y,pxs[i],w0b0);
            float w10=fmaf(b0.y,pxs[i],w1b0);
            float w20=fmaf(c0.y,pxs[i],w2b0);
            float mn0=fminf(w00,fminf(w10,w20));
            float w01=fmaf(a1.y,pxs[i],w0b1);
            float w11=fmaf(b1.y,pxs[i],w1b1);
            float w21=fmaf(c1.y,pxs[i],w2b1);
            float mn1=fminf(w01,fminf(w11,w21));
            mm[i]=fmaxf(mm[i],fmaxf(mn0,mn1));
            float z0=fmaf(b0.w,pxs[i],zb0);
            if(mn0>=-1e-6f && z0>bzv[i]){ bzv[i]=z0; biv[i]=f; }
            float z1=fmaf(b1.w,pxs[i],zb1);
            if(mn1>=-1e-6f && z1>bzv[i]){ bzv[i]=z1; biv[i]=f+1; }
        }
    }
    if(f<m){
        float4 a=s0[f], b=s1[f], c=s2[f];
        float w0b=fmaf(a.z,pyv,a.x);
        float w1b=fmaf(b.z,pyv,b.x);
        float w2b=fmaf(c.z,pyv,c.x);
        float zb =fmaf(c.w,pyv,a.w);
        #pragma unroll
        for(int i=0;i<5;i++){
            float w0=fmaf(a.y,pxs[i],w0b);
            float w1=fmaf(b.y,pxs[i],w1b);
            float w2=fmaf(c.y,pxs[i],w2b);
            float mn=fminf(w0,fminf(w1,w2));
            mm[i]=fmaxf(mm[i],mn);
            float z=fmaf(b.w,pxs[i],zb);
            if(mn>=-1e-6f && z>bzv[i]){ bzv[i]=z; biv[i]=f; }
        }
    }

    #pragma unroll
    for(int i=0;i<5;i++){
        int x=tx+32*i;
        float soft=1.0f/(1.0f+expf(-7000.0f*mm[i]));
        g_soft[p*HW + y*IMW + x]=soft;
        float f0=0.f,f1=0.f,f2=0.f;
        if(biv[i]>=0){
            float4 a=s0[biv[i]], b=s1[biv[i]], c=s2[biv[i]];
            float pxv=fmaf((float)x, STEP, -1.0f);
            float w0=fmaf(a.y,pxv,fmaf(a.z,pyv,a.x));
            float w1=fmaf(b.y,pxv,fmaf(b.z,pyv,b.x));
            float w2=fmaf(c.y,pxv,fmaf(c.z,pyv,c.x));
            const float* ff=&ffeat[sid[biv[i]]*9];
            f0=w0*ff[0]+w1*ff[3]+w2*ff[6];
            f1=w0*ff[1]+w1*ff[4]+w2*ff[7];
            f2=w0*ff[2]+w1*ff[5]+w2*ff[8];
        }
        int bo=p*3*HW + y*IMW + x;
        g_feats[bo      ]=f0;
        g_feats[bo+  HW ]=f1;
        g_feats[bo+2*HW ]=f2;
    }
}

// ---------------- post task (16-row tile, rgb blur or mask chain) ----------------
__device__ void post_task(float* bufA, float* bufB, int task, int tile,
                          float* __restrict__ out, int tid){
    int y0=tile*16;
    if(task<48){
        const float* in=&g_feats[task*HW];
        for(int idx=tid; idx<26*160; idx+=256){
            int r=idx/160, x=idx%160;
            int yy=y0-5+r;
            yy = yy<0 ? -yy : (yy>IMH-1 ? 2*(IMH-1)-yy : yy);
            bufA[idx]=in[yy*IMW+x];
        }
        __syncthreads();
        for(int idx=tid; idx<16*160; idx+=256){
            int j=idx/160, x=idx%160;
            float acc=0.f;
            #pragma unroll
            for(int k=0;k<11;k++) acc += c_gauss[k]*bufA[(j+k)*160+x];
            bufB[idx]=acc;
        }
        __syncthreads();
        int p=task/3, c=task%3;
        float* o=&out[(p*4+c)*HW];
        for(int idx=tid; idx<16*160; idx+=256){
            int j=idx/160, x=idx%160;
            float acc=0.f;
            #pragma unroll
            for(int k=0;k<11;k++){
                int xx=x+k-5;
                xx = xx<0 ? -xx : (xx>IMW-1 ? 2*(IMW-1)-xx : xx);
                acc += c_gauss[k]*bufB[j*160+xx];
            }
            o[(y0+j)*IMW+x]=acc;
        }
    } else {
        int p=task-48;
        const float* in=&g_soft[p*HW];
        for(int idx=tid; idx<38*160; idx+=256){
            int r=idx/160, x=idx%160;
            int yy=y0-11+r;
            if(yy>=0 && yy<IMH) bufA[idx]=in[yy*IMW+x];
        }
        __syncthreads();
        for(int idx=tid; idx<36*160; idx+=256){
            int r=idx/160, x=idx%160;
            int yy=y0-10+r;
            if(yy<0 || yy>=IMH) continue;
            float mval=3.4e38f;
            #pragma unroll
            for(int dy=-1;dy<=1;dy++){
                int ry=yy+dy; if(ry<0||ry>=IMH) continue;
                int sr=ry-(y0-11);
                #pragma unroll
                for(int dx=-1;dx<=1;dx++){
                    int xx=x+dx; if(xx<0||xx>=IMW) continue;
                    mval=fminf(mval, bufA[sr*160+xx]);
                }
            }
            bufB[idx]=mval;
        }
        __syncthreads();
        for(int idx=tid; idx<26*160; idx+=256){
            int r=idx/160, x=idx%160;
            int yb=y0-5+r;
            if(yb<0 || yb>=IMH) continue;
            float acc=0.f;
            #pragma unroll
            for(int k=0;k<11;k++){
                int yy=yb+k-5;
                yy = yy<0 ? -yy : (yy>IMH-1 ? 2*(IMH-1)-yy : yy);
                acc += c_gauss[k]*bufB[(yy-(y0-10))*160+x];
            }
            bufA[idx]=acc;
        }
        __syncthreads();
        for(int idx=tid; idx<26*160; idx+=256){
            int r=idx/160, x=idx%160;
            int yb=y0-5+r;
            if(yb<0 || yb>=IMH) continue;
            float acc=0.f;
            #pragma unroll
            for(int k=0;k<11;k++){
                int xx=x+k-5;
                xx = xx<0 ? -xx : (xx>IMW-1 ? 2*(IMW-1)-xx : xx);
                acc += c_gauss[k]*bufA[r*160+xx];
            }
            bufB[idx]=acc;
        }
        __syncthreads();
        for(int idx=tid; idx<16*160; idx+=256){
            int j=idx/160, x=idx%160;
            int yb=y0+j;
            float acc=0.f;
            #pragma unroll
            for(int k=0;k<11;k++){
                int yy=yb+k-5;
                yy = yy<0 ? -yy : (yy>IMH-1 ? 2*(IMH-1)-yy : yy);
                acc += c_gauss[k]*bufB[(yy-(y0-5))*160+x];
            }
            bufA[idx]=acc;
        }
        __syncthreads();
        float* o=&out[(p*4+3)*HW];
        for(int idx=tid; idx<16*160; idx+=256){
            int j=idx/160, x=idx%160;
            float acc=0.f;
            #pragma unroll
            for(int k=0;k<11;k++){
                int xx=x+k-5;
                xx = xx<0 ? -xx : (xx>IMW-1 ? 2*(IMW-1)-xx : xx);
                acc += c_gauss[k]*bufA[j*160+xx];
            }
            o[(y0+j)*IMW+x]=acc;
        }
    }
}

// ---------------- unified single-launch kernel ----------------
struct GeomRaster {
    float  sv[NVERT*3];
    float4 s0[NFACE], s1[NFACE], s2[NFACE];
    int    sid[NFACE];
    float  R[9], T[3];
    int    warp_cnt[8], warp_off[8], chunk_base;
};
struct Post { float bufA[38*160]; float bufB[36*160]; };
union UShared { GeomRaster g; Post p; };

__global__ void __launch_bounds__(256,3) k_all(const float* __restrict__ uv,
                                               const int* __restrict__ faces,
                                               const float* __restrict__ quat,
                                               const float* __restrict__ trans,
                                               const float* __restrict__ ffeat,
                                               float* __restrict__ out){
    __shared__ UShared u;
    int bx=blockIdx.x;
    int p=bx/20, band=bx%20, y0=band*8;
    int tid=threadIdx.x;
    int tx=tid&31, ty=tid>>5;
    int lane=tid&31, wid=tid>>5;

    // ---- phase 1: per-block geometry ----
    if(tid==0){
        compute_RT(p, quat, trans, u.g.R, u.g.T);
        u.g.chunk_base=0;
    }
    __syncthreads();
    for(int n=tid; n<NVERT; n+=256){
        float ux=uv[n*3+0], uy=uv[n*3+1], uz=uv[n*3+2];
        u.g.sv[n*3+0]=u.g.R[0]*ux+u.g.R[1]*uy+u.g.R[2]*uz + u.g.T[0];
        u.g.sv[n*3+1]=u.g.R[3]*ux+u.g.R[4]*uy+u.g.R[5]*uz + u.g.T[1];
        u.g.sv[n*3+2]=u.g.R[6]*ux+u.g.R[7]*uy+u.g.R[8]*uz + u.g.T[2];
    }
    __syncthreads();

    float pyc = 1.0f - ((float)y0+3.5f)*STEP;
    float pyr = 3.5f*STEP + 1e-4f;
    const float TAU = -0.002f;

    for(int base=0; base<NFACE; base+=256){
        int fidx=base+tid;
        bool keep=false;
        float4 r0,r1,r2;
        if(fidx<NFACE){
            if(face_record(u.g.sv, faces, fidx, r0, r1, r2)){
                float u0=r0.x + fabsf(r0.y) + r0.z*pyc + fabsf(r0.z)*pyr;
                float u1=r1.x + fabsf(r1.y) + r1.z*pyc + fabsf(r1.z)*pyr;
                float u2=r2.x + fabsf(r2.y) + r2.z*pyc + fabsf(r2.z)*pyr;
                keep = fminf(u0,fminf(u1,u2)) >= TAU;
            }
        }
        unsigned bal=__ballot_sync(0xffffffffu, keep);
        if(lane==0) u.g.warp_cnt[wid]=__popc(bal);
        __syncthreads();
        if(tid==0){
            int a=u.g.chunk_base;
            for(int w=0;w<8;w++){ u.g.warp_off[w]=a; a+=u.g.warp_cnt[w]; }
            u.g.chunk_base=a;
        }
        __syncthreads();
        if(keep){
            int pos=u.g.warp_off[wid]+__popc(bal&((1u<<lane)-1u));
            u.g.s0[pos]=r0; u.g.s1[pos]=r1; u.g.s2[pos]=r2; u.g.sid[pos]=fidx;
        }
        __syncthreads();
    }
    int m=u.g.chunk_base;

    // ---- phase 2: raster ----
    raster_pixels(u.g.s0, u.g.s1, u.g.s2, u.g.sid, m, p, y0, tx, ty, ffeat);

    // ---- grid barrier (320 blocks co-resident) ----
    __syncthreads();
    __threadfence();
    if(tid==0){
        unsigned arrival=atomicAdd(&g_count, 1u);
        unsigned target=(arrival/GRID_ALL + 1u)*GRID_ALL;
        while(*((volatile unsigned*)&g_count) < target) __nanosleep(32);
    }
    __syncthreads();

    // ---- phase 3: post (2 tasks per block) ----
    for(int t=bx; t<640; t+=GRID_ALL){
        int tile=t%10, task=t/10;
        __syncthreads();
        post_task(u.p.bufA, u.p.bufB, task, tile, out, tid);
    }
}

// ================= fallback 3-kernel path =================
__global__ void __launch_bounds__(640) k_geom(const float* __restrict__ uv,
                                              const int* __restrict__ faces,
                                              const float* __restrict__ quat,
                                              const float* __restrict__ trans){
    int p=blockIdx.x; int i=threadIdx.x;
    __shared__ float sR[9], sT[3];
    __shared__ float sv[NVERT*3];
    __shared__ int wcnt[20], wbase[20];
    if(i==0) compute_RT(p, quat, trans, sR, sT);
    __syncthreads();
    for(int n=i; n<NVERT; n+=640){
        float ux=uv[n*3+0], uy=uv[n*3+1], uz=uv[n*3+2];
        sv[n*3+0]=sR[0]*ux+sR[1]*uy+sR[2]*uz + sT[0];
        sv[n*3+1]=sR[3]*ux+sR[4]*uy+sR[5]*uz + sT[1];
        sv[n*3+2]=sR[6]*ux+sR[7]*uy+sR[8]*uz + sT[2];
    }
    __syncthreads();
    int lane=i&31, wid=i>>5;
    float4 r0,r1,r2;
    bool valid=face_record(sv, faces, i, r0, r1, r2);
    unsigned bal=__ballot_sync(0xffffffffu, valid);
    if(lane==0) wcnt[wid]=__popc(bal);
    __syncthreads();
    if(i==0){
        int acc=0;
        for(int w=0;w<20;w++){ wbase[w]=acc; acc+=wcnt[w]; }
        g_nvalid[p]=acc;
    }
    __syncthreads();
    if(valid){
        int pos=wbase[wid]+__popc(bal&((1u<<lane)-1u));
        float4* rec=&g_faceb[(p*NFACE+pos)*4];
        rec[0]=r0; rec[1]=r1; rec[2]=r2;
        rec[3]=make_float4(__int_as_float(i), 0.f, 0.f, 0.f);
    }
}

__global__ void __launch_bounds__(256) k_raster_fb(const float* __restrict__ ffeat){
    int p=blockIdx.z;
    int y0=blockIdx.y*8;
    int tx=threadIdx.x;
    int tid=threadIdx.y*32+tx;

    __shared__ float4 s0[NFACE], s1[NFACE], s2[NFACE];
    __shared__ int   sid[NFACE];

    int n=g_nvalid[p];
    const float4* src=&g_faceb[p*NFACE*4];
    for(int i=tid;i<n;i+=256){
        s0[i]=src[4*i+0]; s1[i]=src[4*i+1]; s2[i]=src[4*i+2];
        sid[i]=__float_as_int(src[4*i+3].x);
    }
    __syncthreads();
    raster_pixels(s0, s1, s2, sid, n, p, y0, tx, threadIdx.y, ffeat);
}

__global__ void __launch_bounds__(256) k_post_fb(float* __restrict__ out){
    __shared__ float bufA[38*160];
    __shared__ float bufB[36*160];
    post_task(bufA, bufB, blockIdx.y, blockIdx.x, out, threadIdx.x);
}

// ---------------- launch ----------------
extern "C" void kernel_launch(void* const* d_in, const int* in_sizes, int n_in,
                              void* d_out, int out_size) {
    const float* trans=(const float*)d_in[0];
    const float* quat =(const float*)d_in[1];
    const float* uv   =(const float*)d_in[2];
    const float* ffeat=(const float*)d_in[3];
    const int*   faces=(const int*)  d_in[4];
    float* out=(float*)d_out;

    int dev=0; cudaGetDevice(&dev);
    int nsm=0; cudaDeviceGetAttribute(&nsm, cudaDevAttrMultiProcessorCount, dev);
    int per_sm=0;
    cudaOccupancyMaxActiveBlocksPerMultiprocessor(&per_sm, k_all, 256, 0);
    if((long)per_sm*nsm >= GRID_ALL){
        k_all<<<GRID_ALL, 256>>>(uv, faces, quat, trans, ffeat, out);
    } else {
        k_geom<<<NPASS, 640>>>(uv, faces, quat, trans);
        k_raster_fb<<<dim3(1,20,NPASS), dim3(32,8)>>>(ffeat);
        k_post_fb<<<dim3(10,64), 256>>>(out);
    }
}

// round 13
// speedup vs baseline: 1.6561x; 1.0390x over previous
#include <cuda_runtime.h>
#include <math.h>

#define NPASS 16
#define NFACE 640
#define NPAIR 320
#define NVERT 642
#define IMH 160
#define IMW 160
#define HW (IMH*IMW)
#define STEP (2.0f/159.0f)
#define GRID_ALL 320

// gaussian 11-tap weights (fp64 exp/normalize, rounded to float)
#define G0 1.4867195e-06f
#define G1 1.3383023e-04f
#define G2 4.4318484e-03f
#define G3 5.3990966e-02f
#define G4 2.4197073e-01f
#define G5 3.9894228e-01f
__device__ __constant__ float c_gauss[11]={G0,G1,G2,G3,G4,G5,G4,G3,G2,G1,G0};

typedef unsigned long long ull;

// packed f32x2 helpers
#define FMA2(d,a,b,c) asm("fma.rn.f32x2 %0, %1, %2, %3;" : "=l"(d) : "l"(a), "l"(b), "l"(c))
#define PK2(d,x) { unsigned _u=__float_as_uint(x); asm("mov.b64 %0, {%1,%2};" : "=l"(d) : "r"(_u), "r"(_u)); }
#define UPK(lo,hi,v) { unsigned _a,_b; asm("mov.b64 {%0,%1}, %2;" : "=r"(_a), "=r"(_b) : "l"(v)); lo=__uint_as_float(_a); hi=__uint_as_float(_b); }

// ---------------- scratch ----------------
__device__ float4 g_faceb[NPASS*NFACE*4];   // fallback path only
__device__ int    g_nvalid[NPASS];          // fallback path only
__device__ float  g_feats[NPASS*3*HW];
__device__ float  g_soft[NPASS*HW];
__device__ unsigned g_count = 0;            // persistent grid-barrier ticket

// ---------------- helpers ----------------
__device__ void quat_rod(const float* q, float scale, float* R){
    float w=q[0], x=q[1], y=q[2], z=q[3];
    float sn=sqrtf(x*x+y*y+z*z);
    float tt = 2.0f*((w<0.0f)? atan2f(-sn,-w) : atan2f(sn,w));
    float k = (sn>1e-8f)? (tt/fmaxf(sn,1e-8f)) : 2.0f;
    k *= scale;
    float ax=x*k, ay=y*k, az=z*k;
    float th=sqrtf(ax*ax+ay*ay+az*az);
    float inv=1.0f/fmaxf(th,1e-8f);
    float ux=ax*inv, uy=ay*inv, uz=az*inv;
    float s=sinf(th), c=cosf(th), cc=1.0f-c;
    R[0]=1.0f+cc*(-(uy*uy+uz*uz)); R[1]=-s*uz+cc*(ux*uy);          R[2]= s*uy+cc*(ux*uz);
    R[3]= s*uz+cc*(ux*uy);         R[4]=1.0f+cc*(-(ux*ux+uz*uz));  R[5]=-s*ux+cc*(uy*uz);
    R[6]=-s*uy+cc*(ux*uz);         R[7]= s*ux+cc*(uy*uz);          R[8]=1.0f+cc*(-(ux*ux+uy*uy));
}

__device__ void compute_RT(int p, const float* quat, const float* trans,
                           float* sR, float* sT){
    int f=p>>3, st=p&7;
    float R[9], Rs[9];
    quat_rod(&quat[(f*2+1)*4], 1.0f, R);
    quat_rod(&quat[(f*2+0)*4], 1.0f/16.0f, Rs);
    for(int s=0;s<st;s++){
        float Rn[9];
        for(int a=0;a<3;a++)
            for(int b=0;b<3;b++)
                Rn[a*3+b]=R[a*3+0]*Rs[0*3+b]+R[a*3+1]*Rs[1*3+b]+R[a*3+2]*Rs[2*3+b];
        for(int k=0;k<9;k++) R[k]=Rn[k];
    }
    for(int k=0;k<9;k++) sR[k]=R[k];
    float ti=(float)st*(1.0f/7.0f);
    for(int k=0;k<3;k++)
        sT[k]=trans[(f*2+1)*3+k] + ti*trans[(f*2+0)*3+k] - ((k==2)?2.0f:0.0f);
}

// face record with z-plane coefficients packed in .w: (Za,Zb,Zc) in (r0.w,r1.w,r2.w)
__device__ __forceinline__ bool face_record(const float* sv, const int* faces, int i,
                                            float4& r0, float4& r1, float4& r2){
    int i0=faces[i*3+0], i1=faces[i*3+1], i2=faces[i*3+2];
    float ax3=sv[i0*3], ay3=sv[i0*3+1], az3=sv[i0*3+2];
    float bx3=sv[i1*3], by3=sv[i1*3+1], bz3=sv[i1*3+2];
    float cx3=sv[i2*3], cy3=sv[i2*3+1], cz3=sv[i2*3+2];
    float nz=(bx3-ax3)*(cy3-ay3)-(by3-ay3)*(cx3-ax3);
    const float F=(float)(1.0/tan(1.57/4.0));   // exact reference focal (NOT pi/8)
    float ax=(ax3*F)/(-az3), ay=(ay3*F)/(-az3);
    float bx=(bx3*F)/(-bz3), by=(by3*F)/(-bz3);
    float cx=(cx3*F)/(-cz3), cy=(cy3*F)/(-cz3);
    float denom=(bx-ax)*(cy-ay)-(by-ay)*(cx-ax);
    bool valid=(nz>0.0f)&&(fabsf(denom)>1e-9f);
    if(valid){
        float inv=1.0f/denom;
        float A0=(bx*cy-by*cx)*inv, B0=(by-cy)*inv, C0=(cx-bx)*inv;
        float A1=(cx*ay-cy*ax)*inv, B1=(cy-ay)*inv, C1=(ax-cx)*inv;
        float A2=(ax*by-ay*bx)*inv, B2=(ay-by)*inv, C2=(bx-ax)*inv;
        float Za=A0*az3+A1*bz3+A2*cz3;
        float Zb=B0*az3+B1*bz3+B2*cz3;
        float Zc=C0*az3+C1*bz3+C2*cz3;
        r0=make_float4(A0,B0,C0,Za);
        r1=make_float4(A1,B1,C1,Zb);
        r2=make_float4(A2,B2,C2,Zc);
    }
    return valid;
}

// store face record 'pos' into pair-interleaved SoA layout.
// layout: 6 float4 arrays of NPAIR records; record k of pair h holds
//   {c2k_f, c2k_g, c2k+1_f, c2k+1_g} with coeff order
//   [A0,B0, C0,A1, B1,C1, A2,B2, C2,Za, Zb,Zc]
__device__ __forceinline__ void store_face(float* fv, int pos,
                                           float4 r0, float4 r1, float4 r2){
    int h=pos>>1, o=pos&1, b=h*4+o;
    fv[0*4*NPAIR+b]=r0.x;  fv[0*4*NPAIR+b+2]=r0.y;
    fv[1*4*NPAIR+b]=r0.z;  fv[1*4*NPAIR+b+2]=r1.x;
    fv[2*4*NPAIR+b]=r1.y;  fv[2*4*NPAIR+b+2]=r1.z;
    fv[3*4*NPAIR+b]=r2.x;  fv[3*4*NPAIR+b+2]=r2.y;
    fv[4*4*NPAIR+b]=r2.z;  fv[4*4*NPAIR+b+2]=r0.w;
    fv[5*4*NPAIR+b]=r1.w;  fv[5*4*NPAIR+b+2]=r2.w;
}

// ---------------- raster pixel loop over packed pair layout ----------------
// fv MUST be 16-byte aligned (LDS.128 via ulonglong2)
__device__ void raster_pixels(const float* fv, const int* sid, int m,
                              int p, int y0, int tx, int ty,
                              const float* __restrict__ ffeat){
    int y=y0+ty;
    float pyv = 1.0f - (float)y*STEP;
    float px0 = fmaf((float)tx, STEP, -1.0f);
    float pxs[5];
    #pragma unroll
    for(int i=0;i<5;i++) pxs[i]=px0+(32.0f*STEP)*(float)i;
    ull px2[5], pyv2;
    #pragma unroll
    for(int i=0;i<5;i++) PK2(px2[i], pxs[i]);
    PK2(pyv2, pyv);

    float mm[5], bzv[5]; int biv[5];
    #pragma unroll
    for(int i=0;i<5;i++){ mm[i]=-3.0e38f; bzv[i]=-1e9f; biv[i]=-1; }

    int mp=(m+1)>>1;
    const ulonglong2* V0=(const ulonglong2*)(fv+0*4*NPAIR);
    const ulonglong2* V1=(const ulonglong2*)(fv+1*4*NPAIR);
    const ulonglong2* V2=(const ulonglong2*)(fv+2*4*NPAIR);
    const ulonglong2* V3=(const ulonglong2*)(fv+3*4*NPAIR);
    const ulonglong2* V4=(const ulonglong2*)(fv+4*4*NPAIR);
    const ulonglong2* V5=(const ulonglong2*)(fv+5*4*NPAIR);

    for(int h=0; h<mp; h++){
        ulonglong2 q0=V0[h], q1=V1[h], q2=V2[h], q3=V3[h], q4=V4[h], q5=V5[h];
        // q0={A0,B0} q1={C0,A1} q2={B1,C1} q3={A2,B2} q4={C2,Za} q5={Zb,Zc}
        ull w0b,w1b,w2b,zbp;
        FMA2(w0b, q1.x, pyv2, q0.x);
        FMA2(w1b, q2.y, pyv2, q1.y);
        FMA2(w2b, q4.x, pyv2, q3.x);
        FMA2(zbp, q5.y, pyv2, q4.y);
        #pragma unroll
        for(int i=0;i<5;i++){
            ull w0,w1,w2,zz;
            FMA2(w0, q0.y, px2[i], w0b);
            FMA2(w1, q2.x, px2[i], w1b);
            FMA2(w2, q3.y, px2[i], w2b);
            FMA2(zz, q5.x, px2[i], zbp);
            float w0f,w0g,w1f,w1g,w2f,w2g,zf,zg;
            UPK(w0f,w0g,w0); UPK(w1f,w1g,w1); UPK(w2f,w2g,w2); UPK(zf,zg,zz);
            float mnf=fminf(w0f,fminf(w1f,w2f));
            float mng=fminf(w0g,fminf(w1g,w2g));
            mm[i]=fmaxf(mm[i],fmaxf(mnf,mng));
            if(mnf>=-1e-6f && zf>bzv[i]){ bzv[i]=zf; biv[i]=2*h; }
            if(mng>=-1e-6f && zg>bzv[i]){ bzv[i]=zg; biv[i]=2*h+1; }
        }
    }

    #pragma unroll
    for(int i=0;i<5;i++){
        int x=tx+32*i;
        float soft=1.0f/(1.0f+expf(-7000.0f*mm[i]));
        g_soft[p*HW + y*IMW + x]=soft;
        float f0=0.f,f1=0.f,f2=0.f;
        if(biv[i]>=0){
            int pos=biv[i], hh=pos>>1, b=(hh*4)+(pos&1);
            float A0=fv[b],            B0=fv[b+2];
            float C0=fv[1*4*NPAIR+b],  A1=fv[1*4*NPAIR+b+2];
            float B1=fv[2*4*NPAIR+b],  C1=fv[2*4*NPAIR+b+2];
            float A2=fv[3*4*NPAIR+b],  B2=fv[3*4*NPAIR+b+2];
            float C2=fv[4*4*NPAIR+b];
            float pxv=fmaf((float)x, STEP, -1.0f);
            float w0=fmaf(B0,pxv,fmaf(C0,pyv,A0));
            float w1=fmaf(B1,pxv,fmaf(C1,pyv,A1));
            float w2=fmaf(B2,pxv,fmaf(C2,pyv,A2));
            const float* ff=&ffeat[sid[pos]*9];
            f0=w0*ff[0]+w1*ff[3]+w2*ff[6];
            f1=w0*ff[1]+w1*ff[4]+w2*ff[7];
            f2=w0*ff[2]+w1*ff[5]+w2*ff[8];
        }
        int bo=p*3*HW + y*IMW + x;
        g_feats[bo      ]=f0;
        g_feats[bo+  HW ]=f1;
        g_feats[bo+2*HW ]=f2;
    }
}

// ---------------- post task (16-row tile, rgb blur or mask chain) ----------------
__device__ void post_task(float* bufA, float* bufB, int task, int tile,
                          float* __restrict__ out, int tid){
    int y0=tile*16;
    if(task<48){
        const float* in=&g_feats[task*HW];
        for(int idx=tid; idx<26*160; idx+=256){
            int r=idx/160, x=idx%160;
            int yy=y0-5+r;
            yy = yy<0 ? -yy : (yy>IMH-1 ? 2*(IMH-1)-yy : yy);
            bufA[idx]=in[yy*IMW+x];
        }
        __syncthreads();
        for(int idx=tid; idx<16*160; idx+=256){
            int j=idx/160, x=idx%160;
            float acc=0.f;
            #pragma unroll
            for(int k=0;k<11;k++) acc += c_gauss[k]*bufA[(j+k)*160+x];
            bufB[idx]=acc;
        }
        __syncthreads();
        int p=task/3, c=task%3;
        float* o=&out[(p*4+c)*HW];
        for(int idx=tid; idx<16*160; idx+=256){
            int j=idx/160, x=idx%160;
            float acc=0.f;
            #pragma unroll
            for(int k=0;k<11;k++){
                int xx=x+k-5;
                xx = xx<0 ? -xx : (xx>IMW-1 ? 2*(IMW-1)-xx : xx);
                acc += c_gauss[k]*bufB[j*160+xx];
            }
            o[(y0+j)*IMW+x]=acc;
        }
    } else {
        int p=task-48;
        const float* in=&g_soft[p*HW];
        for(int idx=tid; idx<38*160; idx+=256){
            int r=idx/160, x=idx%160;
            int yy=y0-11+r;
            if(yy>=0 && yy<IMH) bufA[idx]=in[yy*IMW+x];
        }
        __syncthreads();
        for(int idx=tid; idx<36*160; idx+=256){
            int r=idx/160, x=idx%160;
            int yy=y0-10+r;
            if(yy<0 || yy>=IMH) continue;
            float mval=3.4e38f;
            #pragma unroll
            for(int dy=-1;dy<=1;dy++){
                int ry=yy+dy; if(ry<0||ry>=IMH) continue;
                int sr=ry-(y0-11);
                #pragma unroll
                for(int dx=-1;dx<=1;dx++){
                    int xx=x+dx; if(xx<0||xx>=IMW) continue;
                    mval=fminf(mval, bufA[sr*160+xx]);
                }
            }
            bufB[idx]=mval;
        }
        __syncthreads();
        for(int idx=tid; idx<26*160; idx+=256){
            int r=idx/160, x=idx%160;
            int yb=y0-5+r;
            if(yb<0 || yb>=IMH) continue;
            float acc=0.f;
            #pragma unroll
            for(int k=0;k<11;k++){
                int yy=yb+k-5;
                yy = yy<0 ? -yy : (yy>IMH-1 ? 2*(IMH-1)-yy : yy);
                acc += c_gauss[k]*bufB[(yy-(y0-10))*160+x];
            }
            bufA[idx]=acc;
        }
        __syncthreads();
        for(int idx=tid; idx<26*160; idx+=256){
            int r=idx/160, x=idx%160;
            int yb=y0-5+r;
            if(yb<0 || yb>=IMH) continue;
            float acc=0.f;
            #pragma unroll
            for(int k=0;k<11;k++){
                int xx=x+k-5;
                xx = xx<0 ? -xx : (xx>IMW-1 ? 2*(IMW-1)-xx : xx);
                acc += c_gauss[k]*bufA[r*160+xx];
            }
            bufB[idx]=acc;
        }
        __syncthreads();
        for(int idx=tid; idx<16*160; idx+=256){
            int j=idx/160, x=idx%160;
            int yb=y0+j;
            float acc=0.f;
            #pragma unroll
            for(int k=0;k<11;k++){
                int yy=yb+k-5;
                yy = yy<0 ? -yy : (yy>IMH-1 ? 2*(IMH-1)-yy : yy);
                acc += c_gauss[k]*bufB[(yy-(y0-5))*160+x];
            }
            bufA[idx]=acc;
        }
        __syncthreads();
        float* o=&out[(p*4+3)*HW];
        for(int idx=tid; idx<16*160; idx+=256){
            int j=idx/160, x=idx%160;
            float acc=0.f;
            #pragma unroll
            for(int k=0;k<11;k++){
                int xx=x+k-5;
                xx = xx<0 ? -xx : (xx>IMW-1 ? 2*(IMW-1)-xx : xx);
                acc += c_gauss[k]*bufA[j*160+xx];
            }
            o[(y0+j)*IMW+x]=acc;
        }
    }
}

// ---------------- unified single-launch kernel ----------------
// fv FIRST so it sits at offset 0 of the 16B-aligned union (LDS.128 alignment)
struct __align__(16) GeomRaster {
    float  fv[6*4*NPAIR];          // pair-interleaved SoA face records (30720B), 16B-aligned
    float  sv[NVERT*3];
    int    sid[NFACE+1];
    float  R[9], T[3];
    int    warp_cnt[8], warp_off[8], chunk_base;
};
struct __align__(16) Post { float bufA[38*160]; float bufB[36*160]; };
union __align__(16) UShared { GeomRaster g; Post p; };

__global__ void __launch_bounds__(256,3) k_all(const float* __restrict__ uv,
                                               const int* __restrict__ faces,
                                               const float* __restrict__ quat,
                                               const float* __restrict__ trans,
                                               const float* __restrict__ ffeat,
                                               float* __restrict__ out){
    __shared__ UShared u;
    int bx=blockIdx.x;
    int p=bx/20, band=bx%20, y0=band*8;
    int tid=threadIdx.x;
    int tx=tid&31, ty=tid>>5;
    int lane=tid&31, wid=tid>>5;

    // ---- phase 1: per-block geometry ----
    if(tid==0){
        compute_RT(p, quat, trans, u.g.R, u.g.T);
        u.g.chunk_base=0;
    }
    __syncthreads();
    for(int n=tid; n<NVERT; n+=256){
        float ux=uv[n*3+0], uy=uv[n*3+1], uz=uv[n*3+2];
        u.g.sv[n*3+0]=u.g.R[0]*ux+u.g.R[1]*uy+u.g.R[2]*uz + u.g.T[0];
        u.g.sv[n*3+1]=u.g.R[3]*ux+u.g.R[4]*uy+u.g.R[5]*uz + u.g.T[1];
        u.g.sv[n*3+2]=u.g.R[6]*ux+u.g.R[7]*uy+u.g.R[8]*uz + u.g.T[2];
    }
    __syncthreads();

    float pyc = 1.0f - ((float)y0+3.5f)*STEP;
    float pyr = 3.5f*STEP + 1e-4f;
    const float TAU = -0.002f;

    for(int base=0; base<NFACE; base+=256){
        int fidx=base+tid;
        bool keep=false;
        float4 r0,r1,r2;
        if(fidx<NFACE){
            if(face_record(u.g.sv, faces, fidx, r0, r1, r2)){
                float u0=r0.x + fabsf(r0.y) + r0.z*pyc + fabsf(r0.z)*pyr;
                float u1=r1.x + fabsf(r1.y) + r1.z*pyc + fabsf(r1.z)*pyr;
                float u2=r2.x + fabsf(r2.y) + r2.z*pyc + fabsf(r2.z)*pyr;
                keep = fminf(u0,fminf(u1,u2)) >= TAU;
            }
        }
        unsigned bal=__ballot_sync(0xffffffffu, keep);
        if(lane==0) u.g.warp_cnt[wid]=__popc(bal);
        __syncthreads();
        if(tid==0){
            int a=u.g.chunk_base;
            for(int w=0;w<8;w++){ u.g.warp_off[w]=a; a+=u.g.warp_cnt[w]; }
            u.g.chunk_base=a;
        }
        __syncthreads();
        if(keep){
            int pos=u.g.warp_off[wid]+__popc(bal&((1u<<lane)-1u));
            store_face(u.g.fv, pos, r0, r1, r2);
            u.g.sid[pos]=fidx;
        }
        __syncthreads();
    }
    int m=u.g.chunk_base;
    // odd-m sentinel pad (never passes inside-test, mm contribution -1e9)
    if(tid==0 && (m&1)){
        float4 s0=make_float4(-1e9f,0.f,0.f,0.f);
        store_face(u.g.fv, m, s0, s0, s0);
        u.g.sid[m]=0;
    }
    __syncthreads();

    // ---- phase 2: raster ----
    raster_pixels(u.g.fv, u.g.sid, m, p, y0, tx, ty, ffeat);

    // ---- grid barrier (320 blocks co-resident) ----
    __syncthreads();
    __threadfence();
    if(tid==0){
        unsigned arrival=atomicAdd(&g_count, 1u);
        unsigned target=(arrival/GRID_ALL + 1u)*GRID_ALL;
        while(*((volatile unsigned*)&g_count) < target) __nanosleep(32);
    }
    __syncthreads();

    // ---- phase 3: post (2 tasks per block) ----
    for(int t=bx; t<640; t+=GRID_ALL){
        int tile=t%10, task=t/10;
        __syncthreads();
        post_task(u.p.bufA, u.p.bufB, task, tile, out, tid);
    }
}

// ================= fallback 3-kernel path =================
__global__ void __launch_bounds__(640) k_geom(const float* __restrict__ uv,
                                              const int* __restrict__ faces,
                                              const float* __restrict__ quat,
                                              const float* __restrict__ trans){
    int p=blockIdx.x; int i=threadIdx.x;
    __shared__ float sR[9], sT[3];
    __shared__ float sv[NVERT*3];
    __shared__ int wcnt[20], wbase[20];
    if(i==0) compute_RT(p, quat, trans, sR, sT);
    __syncthreads();
    for(int n=i; n<NVERT; n+=640){
        float ux=uv[n*3+0], uy=uv[n*3+1], uz=uv[n*3+2];
        sv[n*3+0]=sR[0]*ux+sR[1]*uy+sR[2]*uz + sT[0];
        sv[n*3+1]=sR[3]*ux+sR[4]*uy+sR[5]*uz + sT[1];
        sv[n*3+2]=sR[6]*ux+sR[7]*uy+sR[8]*uz + sT[2];
    }
    __syncthreads();
    int lane=i&31, wid=i>>5;
    float4 r0,r1,r2;
    bool valid=face_record(sv, faces, i, r0, r1, r2);
    unsigned bal=__ballot_sync(0xffffffffu, valid);
    if(lane==0) wcnt[wid]=__popc(bal);
    __syncthreads();
    if(i==0){
        int acc=0;
        for(int w=0;w<20;w++){ wbase[w]=acc; acc+=wcnt[w]; }
        g_nvalid[p]=acc;
    }
    __syncthreads();
    if(valid){
        int pos=wbase[wid]+__popc(bal&((1u<<lane)-1u));
        float4* rec=&g_faceb[(p*NFACE+pos)*4];
        rec[0]=r0; rec[1]=r1; rec[2]=r2;
        rec[3]=make_float4(__int_as_float(i), 0.f, 0.f, 0.f);
    }
}

__global__ void __launch_bounds__(256) k_raster_fb(const float* __restrict__ ffeat){
    int p=blockIdx.z;
    int y0=blockIdx.y*8;
    int tx=threadIdx.x;
    int tid=threadIdx.y*32+tx;

    __shared__ __align__(16) float fv[6*4*NPAIR];
    __shared__ int   sid[NFACE+1];

    int n=g_nvalid[p];
    const float4* src=&g_faceb[p*NFACE*4];
    for(int i=tid;i<n;i+=256){
        store_face(fv, i, src[4*i+0], src[4*i+1], src[4*i+2]);
        sid[i]=__float_as_int(src[4*i+3].x);
    }
    if(tid==0 && (n&1)){
        float4 s0=make_float4(-1e9f,0.f,0.f,0.f);
        store_face(fv, n, s0, s0, s0);
        sid[n]=0;
    }
    __syncthreads();
    raster_pixels(fv, sid, n, p, y0, tx, threadIdx.y, ffeat);
}

__global__ void __launch_bounds__(256) k_post_fb(float* __restrict__ out){
    __shared__ __align__(16) float bufA[38*160];
    __shared__ __align__(16) float bufB[36*160];
    post_task(bufA, bufB, blockIdx.y, blockIdx.x, out, threadIdx.x);
}

// ---------------- launch ----------------
extern "C" void kernel_launch(void* const* d_in, const int* in_sizes, int n_in,
                              void* d_out, int out_size) {
    const float* trans=(const float*)d_in[0];
    const float* quat =(const float*)d_in[1];
    const float* uv   =(const float*)d_in[2];
    const float* ffeat=(const float*)d_in[3];
    const int*   faces=(const int*)  d_in[4];
    float* out=(float*)d_out;

    int dev=0; cudaGetDevice(&dev);
    int nsm=0; cudaDeviceGetAttribute(&nsm, cudaDevAttrMultiProcessorCount, dev);
    int per_sm=0;
    cudaOccupancyMaxActiveBlocksPerMultiprocessor(&per_sm, k_all, 256, 0);
    if((long)per_sm*nsm >= GRID_ALL){
        k_all<<<GRID_ALL, 256>>>(uv, faces, quat, trans, ffeat, out);
    } else {
        k_geom<<<NPASS, 640>>>(uv, faces, quat, trans);
        k_raster_fb<<<dim3(1,20,NPASS), dim3(32,8)>>>(ffeat);
        k_post_fb<<<dim3(10,64), 256>>>(out);
    }
}